// round 1
// baseline (speedup 1.0000x reference)
#include <cuda_runtime.h>
#include <math.h>

// Problem constants (fixed by the dataset)
#define NROWS 4096
#define DIM   1024
#define MARGIN 0.5f
#define EPSN   1e-8f

// Scratch (no allocations allowed in kernel_launch)
__device__ float g_rnorm_img[NROWS];   // 1 / max(||img_i||, eps)
__device__ float g_rnorm_txt[NROWS];   // 1 / max(||txt_j||, eps)
__device__ float g_loss_pos;
__device__ float g_loss_neg;

__inline__ __device__ float warp_sum(float v) {
    #pragma unroll
    for (int o = 16; o > 0; o >>= 1) v += __shfl_down_sync(0xffffffffu, v, o);
    return v;
}

__global__ void init_accum_kernel() {
    g_loss_pos = 0.0f;
    g_loss_neg = 0.0f;
}

// One block per row: ||img||^2, ||txt||^2, dot(img, txt) -> rnorms + positive loss
__global__ void __launch_bounds__(256) row_stats_kernel(
    const float* __restrict__ img, const float* __restrict__ txt)
{
    const int row = blockIdx.x;
    const float4* ip = reinterpret_cast<const float4*>(img + (size_t)row * DIM);
    const float4* tp = reinterpret_cast<const float4*>(txt + (size_t)row * DIM);

    float si = 0.f, st = 0.f, sd = 0.f;
    // DIM/4 = 256 float4 per row, blockDim = 256 -> exactly one per thread
    {
        int k = threadIdx.x;
        float4 a = ip[k];
        float4 b = tp[k];
        si += a.x*a.x + a.y*a.y + a.z*a.z + a.w*a.w;
        st += b.x*b.x + b.y*b.y + b.z*b.z + b.w*b.w;
        sd += a.x*b.x + a.y*b.y + a.z*b.z + a.w*b.w;
    }

    __shared__ float sh[3][8];
    int lane = threadIdx.x & 31;
    int wid  = threadIdx.x >> 5;
    si = warp_sum(si); st = warp_sum(st); sd = warp_sum(sd);
    if (lane == 0) { sh[0][wid] = si; sh[1][wid] = st; sh[2][wid] = sd; }
    __syncthreads();
    if (wid == 0) {
        si = (lane < 8) ? sh[0][lane] : 0.f;
        st = (lane < 8) ? sh[1][lane] : 0.f;
        sd = (lane < 8) ? sh[2][lane] : 0.f;
        #pragma unroll
        for (int o = 4; o > 0; o >>= 1) {
            si += __shfl_down_sync(0xffffffffu, si, o);
            st += __shfl_down_sync(0xffffffffu, st, o);
            sd += __shfl_down_sync(0xffffffffu, sd, o);
        }
        if (lane == 0) {
            float ni = fmaxf(sqrtf(si), EPSN);
            float nt = fmaxf(sqrtf(st), EPSN);
            g_rnorm_img[row] = 1.0f / ni;
            g_rnorm_txt[row] = 1.0f / nt;
            float pos = sd / (ni * nt);
            float e = 1.0f - pos;
            atomicAdd(&g_loss_pos, e * e);
        }
    }
}

// 128x128x8 tiled fp32 GEMM; epilogue computes sum(relu(sim - margin)^2)
// with diagonal masked, block-reduced, one atomicAdd per block.
__global__ void __launch_bounds__(256) gemm_loss_kernel(
    const float* __restrict__ A,   // img  [NROWS, DIM]
    const float* __restrict__ B)   // txt  [NROWS, DIM]
{
    __shared__ float As[8][128];
    __shared__ float Bs[8][128];

    const int bi = blockIdx.y * 128;   // img rows
    const int bj = blockIdx.x * 128;   // txt rows
    const int tid = threadIdx.x;
    const int ty = tid >> 4;           // 0..15
    const int tx = tid & 15;           // 0..15

    // loading pattern: each thread loads one float4 per matrix per k-chunk
    const int lr = tid >> 1;           // 0..127 tile row
    const int lc = (tid & 1) * 4;      // 0 or 4 within k-chunk

    float acc[8][8] = {};

    const float* aBase = A + (size_t)(bi + lr) * DIM + lc;
    const float* bBase = B + (size_t)(bj + lr) * DIM + lc;

    for (int k0 = 0; k0 < DIM; k0 += 8) {
        float4 a = *reinterpret_cast<const float4*>(aBase + k0);
        float4 b = *reinterpret_cast<const float4*>(bBase + k0);
        As[lc + 0][lr] = a.x; As[lc + 1][lr] = a.y;
        As[lc + 2][lr] = a.z; As[lc + 3][lr] = a.w;
        Bs[lc + 0][lr] = b.x; Bs[lc + 1][lr] = b.y;
        Bs[lc + 2][lr] = b.z; Bs[lc + 3][lr] = b.w;
        __syncthreads();

        #pragma unroll
        for (int k = 0; k < 8; k++) {
            float4 ra0 = *reinterpret_cast<const float4*>(&As[k][ty * 8]);
            float4 ra1 = *reinterpret_cast<const float4*>(&As[k][ty * 8 + 4]);
            float4 rb0 = *reinterpret_cast<const float4*>(&Bs[k][tx * 8]);
            float4 rb1 = *reinterpret_cast<const float4*>(&Bs[k][tx * 8 + 4]);
            float ra[8] = {ra0.x, ra0.y, ra0.z, ra0.w, ra1.x, ra1.y, ra1.z, ra1.w};
            float rb[8] = {rb0.x, rb0.y, rb0.z, rb0.w, rb1.x, rb1.y, rb1.z, rb1.w};
            #pragma unroll
            for (int i = 0; i < 8; i++)
                #pragma unroll
                for (int j = 0; j < 8; j++)
                    acc[i][j] = fmaf(ra[i], rb[j], acc[i][j]);
        }
        __syncthreads();
    }

    // Epilogue: normalized sim, margin, diagonal mask, local sum
    float ri[8], rj[8];
    #pragma unroll
    for (int i = 0; i < 8; i++) ri[i] = g_rnorm_img[bi + ty * 8 + i];
    #pragma unroll
    for (int j = 0; j < 8; j++) rj[j] = g_rnorm_txt[bj + tx * 8 + j];

    float local = 0.f;
    #pragma unroll
    for (int i = 0; i < 8; i++) {
        int gi = bi + ty * 8 + i;
        #pragma unroll
        for (int j = 0; j < 8; j++) {
            int gj = bj + tx * 8 + j;
            float s = acc[i][j] * ri[i] * rj[j];
            float d = s - MARGIN;
            if (gi != gj && d > 0.f) local += d * d;
        }
    }

    // Block reduction
    __shared__ float red[8];
    int lane = tid & 31, wid = tid >> 5;
    local = warp_sum(local);
    if (lane == 0) red[wid] = local;
    __syncthreads();
    if (wid == 0) {
        local = (lane < 8) ? red[lane] : 0.f;
        #pragma unroll
        for (int o = 4; o > 0; o >>= 1)
            local += __shfl_down_sync(0xffffffffu, local, o);
        if (lane == 0 && local != 0.f) atomicAdd(&g_loss_neg, local);
    }
}

__global__ void finalize_kernel(float* __restrict__ out) {
    const float n = (float)NROWS;
    out[0] = g_loss_pos / n + g_loss_neg / (n * n);
}

extern "C" void kernel_launch(void* const* d_in, const int* in_sizes, int n_in,
                              void* d_out, int out_size) {
    const float* img = (const float*)d_in[0];
    const float* txt = (const float*)d_in[1];
    float* out = (float*)d_out;

    init_accum_kernel<<<1, 1>>>();
    row_stats_kernel<<<NROWS, 256>>>(img, txt);
    dim3 grid(NROWS / 128, NROWS / 128);
    gemm_loss_kernel<<<grid, 256>>>(img, txt);
    finalize_kernel<<<1, 1>>>(out);
}

// round 3
// speedup vs baseline: 6.1009x; 6.1009x over previous
#include <cuda_runtime.h>
#include <cuda_bf16.h>
#include <cstdint>
#include <math.h>

#define NROWS 4096
#define DIM   1024
#define MARGIN 0.5f
#define EPSN   1e-8f

#define BM 128
#define BN 128
#define BK 32
#define KT (DIM / BK)        // 32
#define STAGES 3
#define SROW 80              // padded smem row stride (bytes) for 64B of data
#define STAGE_A (BM * SROW)  // 10240
#define STAGE_B (BN * SROW)  // 10240
#define STAGE_BYTES (STAGE_A + STAGE_B)
#define SMEM_BYTES (STAGES * STAGE_BYTES)   // 61440

// Scratch
__device__ __nv_bfloat16 g_img_bf[NROWS * DIM];
__device__ __nv_bfloat16 g_txt_bf[NROWS * DIM];
__device__ float g_rnorm_img[NROWS];
__device__ float g_rnorm_txt[NROWS];
__device__ float g_loss_pos;
__device__ float g_loss_neg;

__device__ __forceinline__ uint32_t smem_u32(const void* p) {
    uint32_t a;
    asm("{ .reg .u64 t; cvta.to.shared.u64 t, %1; cvt.u32.u64 %0, t; }" : "=r"(a) : "l"(p));
    return a;
}

__device__ __forceinline__ float warp_sum(float v) {
    #pragma unroll
    for (int o = 16; o > 0; o >>= 1) v += __shfl_down_sync(0xffffffffu, v, o);
    return v;
}

__global__ void init_accum_kernel() { g_loss_pos = 0.0f; g_loss_neg = 0.0f; }

// Fused: fp32 read -> bf16 copies + norms + positive loss. One block per row.
__global__ void __launch_bounds__(256) row_stats_convert_kernel(
    const float* __restrict__ img, const float* __restrict__ txt)
{
    const int row = blockIdx.x;
    const int k = threadIdx.x;                        // 256 threads, 1 float4 each
    const float4 a = reinterpret_cast<const float4*>(img + (size_t)row * DIM)[k];
    const float4 b = reinterpret_cast<const float4*>(txt + (size_t)row * DIM)[k];

    __nv_bfloat162* ib = reinterpret_cast<__nv_bfloat162*>(g_img_bf + (size_t)row * DIM);
    __nv_bfloat162* tb = reinterpret_cast<__nv_bfloat162*>(g_txt_bf + (size_t)row * DIM);
    ib[2 * k]     = __floats2bfloat162_rn(a.x, a.y);
    ib[2 * k + 1] = __floats2bfloat162_rn(a.z, a.w);
    tb[2 * k]     = __floats2bfloat162_rn(b.x, b.y);
    tb[2 * k + 1] = __floats2bfloat162_rn(b.z, b.w);

    float si = a.x*a.x + a.y*a.y + a.z*a.z + a.w*a.w;
    float st = b.x*b.x + b.y*b.y + b.z*b.z + b.w*b.w;
    float sd = a.x*b.x + a.y*b.y + a.z*b.z + a.w*b.w;

    __shared__ float sh[3][8];
    int lane = threadIdx.x & 31, wid = threadIdx.x >> 5;
    si = warp_sum(si); st = warp_sum(st); sd = warp_sum(sd);
    if (lane == 0) { sh[0][wid] = si; sh[1][wid] = st; sh[2][wid] = sd; }
    __syncthreads();
    if (wid == 0) {
        si = (lane < 8) ? sh[0][lane] : 0.f;
        st = (lane < 8) ? sh[1][lane] : 0.f;
        sd = (lane < 8) ? sh[2][lane] : 0.f;
        #pragma unroll
        for (int o = 4; o > 0; o >>= 1) {
            si += __shfl_down_sync(0xffffffffu, si, o);
            st += __shfl_down_sync(0xffffffffu, st, o);
            sd += __shfl_down_sync(0xffffffffu, sd, o);
        }
        if (lane == 0) {
            float ni = fmaxf(sqrtf(si), EPSN);
            float nt = fmaxf(sqrtf(st), EPSN);
            g_rnorm_img[row] = 1.0f / ni;
            g_rnorm_txt[row] = 1.0f / nt;
            float e = 1.0f - sd / (ni * nt);
            atomicAdd(&g_loss_pos, e * e);
        }
    }
}

#define CP_ASYNC16(dst, src) \
    asm volatile("cp.async.cg.shared.global [%0], [%1], 16;" :: "r"(dst), "l"(src) : "memory")
#define CP_COMMIT()  asm volatile("cp.async.commit_group;" ::: "memory")
#define CP_WAIT2()   asm volatile("cp.async.wait_group 2;" ::: "memory")

#define LDSM_X4(r0, r1, r2, r3, addr) \
    asm volatile("ldmatrix.sync.aligned.m8n8.x4.shared.b16 {%0,%1,%2,%3}, [%4];" \
        : "=r"(r0), "=r"(r1), "=r"(r2), "=r"(r3) : "r"(addr))

#define MMA_BF16(c, a, b) \
    asm volatile("mma.sync.aligned.m16n8k16.row.col.f32.bf16.bf16.f32 " \
        "{%0,%1,%2,%3}, {%4,%5,%6,%7}, {%8,%9}, {%0,%1,%2,%3};" \
        : "+f"((c)[0]), "+f"((c)[1]), "+f"((c)[2]), "+f"((c)[3]) \
        : "r"((a)[0]), "r"((a)[1]), "r"((a)[2]), "r"((a)[3]), "r"((b)[0]), "r"((b)[1]))

__device__ __forceinline__ void prefetch_stage(uint32_t sa, uint32_t sb, int bi, int bj,
                                               int kt, int tid)
{
    const int r  = tid >> 1;            // 0..127
    const int c0 = (tid & 1) * 2;       // chunks c0, c0+1 of 4 (16B each)
    const __nv_bfloat16* asrc = g_img_bf + (size_t)(bi + r) * DIM + kt * BK + c0 * 8;
    const __nv_bfloat16* bsrc = g_txt_bf + (size_t)(bj + r) * DIM + kt * BK + c0 * 8;
    uint32_t da = sa + r * SROW + c0 * 16;
    uint32_t db = sb + r * SROW + c0 * 16;
    CP_ASYNC16(da,      asrc);
    CP_ASYNC16(da + 16, asrc + 8);
    CP_ASYNC16(db,      bsrc);
    CP_ASYNC16(db + 16, bsrc + 8);
}

__global__ void __launch_bounds__(256, 2) gemm_neg_kernel()
{
    extern __shared__ char smem[];
    const uint32_t sbase = smem_u32(smem);
    const int tid  = threadIdx.x;
    const int lane = tid & 31;
    const int wid  = tid >> 5;
    const int wm   = (wid >> 2) * 64;   // warp m offset (0 or 64)
    const int wn   = (wid & 3) * 32;    // warp n offset (0,32,64,96)

    const int bi = blockIdx.y * BM;
    const int bj = blockIdx.x * BN;

    uint32_t sA[STAGES], sB[STAGES];
    #pragma unroll
    for (int s = 0; s < STAGES; ++s) {
        sA[s] = sbase + s * STAGE_BYTES;
        sB[s] = sA[s] + STAGE_A;
    }

    float acc[4][4][4];
    #pragma unroll
    for (int i = 0; i < 4; ++i)
        #pragma unroll
        for (int j = 0; j < 4; ++j)
            #pragma unroll
            for (int k = 0; k < 4; ++k) acc[i][j][k] = 0.f;

    #pragma unroll
    for (int s = 0; s < STAGES; ++s) {
        prefetch_stage(sA[s], sB[s], bi, bj, s, tid);
        CP_COMMIT();
    }

    // ldmatrix lane addressing (within a stage)
    const int a_row   = lane & 15;
    const int a_chunk = lane >> 4;            // 0 or 1 (k halves)
    const int b_row   = (lane & 7) + ((lane >> 4) << 3);
    const int b_chunk = (lane >> 3) & 1;

    for (int kt = 0; kt < KT; ++kt) {
        const int st = kt % STAGES;
        CP_WAIT2();
        __syncthreads();

        #pragma unroll
        for (int k16 = 0; k16 < 2; ++k16) {
            uint32_t af[4][4], bf[4][2];
            #pragma unroll
            for (int mf = 0; mf < 4; ++mf) {
                uint32_t addr = sA[st] + (wm + mf * 16 + a_row) * SROW
                              + (a_chunk + k16 * 2) * 16;
                LDSM_X4(af[mf][0], af[mf][1], af[mf][2], af[mf][3], addr);
            }
            #pragma unroll
            for (int nf2 = 0; nf2 < 2; ++nf2) {
                uint32_t addr = sB[st] + (wn + nf2 * 16 + b_row) * SROW
                              + (b_chunk + k16 * 2) * 16;
                uint32_t r0, r1, r2, r3;
                LDSM_X4(r0, r1, r2, r3, addr);
                bf[nf2 * 2][0] = r0;     bf[nf2 * 2][1] = r1;
                bf[nf2 * 2 + 1][0] = r2; bf[nf2 * 2 + 1][1] = r3;
            }
            #pragma unroll
            for (int mf = 0; mf < 4; ++mf)
                #pragma unroll
                for (int nf = 0; nf < 4; ++nf)
                    MMA_BF16(acc[mf][nf], af[mf], bf[nf]);
        }
        __syncthreads();

        if (kt + STAGES < KT)
            prefetch_stage(sA[st], sB[st], bi, bj, kt + STAGES, tid);
        CP_COMMIT();
    }

    // ---- fused loss epilogue ----
    const int groupRow = lane >> 2;        // 0..7
    const int col0 = (lane & 3) * 2;

    float rj[4][2];
    #pragma unroll
    for (int nf = 0; nf < 4; ++nf) {
        int gj = bj + wn + nf * 8 + col0;
        rj[nf][0] = __ldg(&g_rnorm_txt[gj]);
        rj[nf][1] = __ldg(&g_rnorm_txt[gj + 1]);
    }

    float local = 0.f;
    #pragma unroll
    for (int mf = 0; mf < 4; ++mf) {
        int gi0 = bi + wm + mf * 16 + groupRow;
        int gi1 = gi0 + 8;
        float ri0 = __ldg(&g_rnorm_img[gi0]);
        float ri1 = __ldg(&g_rnorm_img[gi1]);
        #pragma unroll
        for (int nf = 0; nf < 4; ++nf) {
            int gj0 = bj + wn + nf * 8 + col0;
            int gj1 = gj0 + 1;
            float s0 = acc[mf][nf][0] * ri0 * rj[nf][0];
            float s1 = acc[mf][nf][1] * ri0 * rj[nf][1];
            float s2 = acc[mf][nf][2] * ri1 * rj[nf][0];
            float s3 = acc[mf][nf][3] * ri1 * rj[nf][1];
            float d0 = s0 - MARGIN, d1 = s1 - MARGIN;
            float d2 = s2 - MARGIN, d3 = s3 - MARGIN;
            if (gi0 != gj0 && d0 > 0.f) local += d0 * d0;
            if (gi0 != gj1 && d1 > 0.f) local += d1 * d1;
            if (gi1 != gj0 && d2 > 0.f) local += d2 * d2;
            if (gi1 != gj1 && d3 > 0.f) local += d3 * d3;
        }
    }

    __shared__ float red[8];
    local = warp_sum(local);
    if (lane == 0) red[wid] = local;
    __syncthreads();
    if (wid == 0) {
        local = (lane < 8) ? red[lane] : 0.f;
        #pragma unroll
        for (int o = 4; o > 0; o >>= 1)
            local += __shfl_down_sync(0xffffffffu, local, o);
        if (lane == 0 && local != 0.f) atomicAdd(&g_loss_neg, local);
    }
}

__global__ void finalize_kernel(float* __restrict__ out) {
    const float n = (float)NROWS;
    out[0] = g_loss_pos / n + g_loss_neg / (n * n);
}

extern "C" void kernel_launch(void* const* d_in, const int* in_sizes, int n_in,
                              void* d_out, int out_size) {
    const float* img = (const float*)d_in[0];
    const float* txt = (const float*)d_in[1];
    float* out = (float*)d_out;

    cudaFuncSetAttribute(gemm_neg_kernel, cudaFuncAttributeMaxDynamicSharedMemorySize, SMEM_BYTES);

    init_accum_kernel<<<1, 1>>>();
    row_stats_convert_kernel<<<NROWS, 256>>>(img, txt);
    dim3 grid(NROWS / BN, NROWS / BM);   // (32, 32)
    gemm_neg_kernel<<<grid, 256, SMEM_BYTES>>>();
    finalize_kernel<<<1, 1>>>(out);
}

// round 4
// speedup vs baseline: 6.9276x; 1.1355x over previous
#include <cuda_runtime.h>
#include <cuda_bf16.h>
#include <cuda_fp8.h>
#include <cstdint>
#include <math.h>

#define NROWS 4096
#define DIM   1024
#define MARGIN 0.5f
#define EPSN   1e-8f

#define BM 128
#define BN 128
#define BK 64                 // 64 fp8 bytes per k-chunk
#define KT (DIM / BK)         // 16
#define STAGES 4
#define SROW 80               // padded smem row stride (bytes) for 64B of data
#define STAGE_A (BM * SROW)
#define STAGE_B (BN * SROW)
#define STAGE_BYTES (STAGE_A + STAGE_B)        // 20480
#define SMEM_BYTES (STAGES * STAGE_BYTES)      // 81920

#define NBLK_I (NROWS / BM)   // 32
#define NBLK_J (NROWS / BN)   // 32

// Scratch (device globals; rewritten every call)
__device__ uint8_t g_img_f8[NROWS * DIM];
__device__ uint8_t g_txt_f8[NROWS * DIM];
__device__ float g_rnorm_img[NROWS];
__device__ float g_rnorm_txt[NROWS];
__device__ float g_pos_part[NROWS];
__device__ float g_neg_part[NBLK_I * NBLK_J];

__device__ __forceinline__ uint32_t smem_u32(const void* p) {
    uint32_t a;
    asm("{ .reg .u64 t; cvta.to.shared.u64 t, %1; cvt.u32.u64 %0, t; }" : "=r"(a) : "l"(p));
    return a;
}

__device__ __forceinline__ float warp_sum(float v) {
    #pragma unroll
    for (int o = 16; o > 0; o >>= 1) v += __shfl_down_sync(0xffffffffu, v, o);
    return v;
}

__device__ __forceinline__ uint32_t pack4_e4m3(float4 v) {
    __nv_fp8x2_storage_t lo = __nv_cvt_float2_to_fp8x2(make_float2(v.x, v.y),
                                                       __NV_SATFINITE, __NV_E4M3);
    __nv_fp8x2_storage_t hi = __nv_cvt_float2_to_fp8x2(make_float2(v.z, v.w),
                                                       __NV_SATFINITE, __NV_E4M3);
    return (uint32_t)lo | ((uint32_t)hi << 16);
}

// Fused: fp32 read -> fp8 copies + norms + positive-loss partial. One block per row.
__global__ void __launch_bounds__(256) row_stats_convert_kernel(
    const float* __restrict__ img, const float* __restrict__ txt)
{
    const int row = blockIdx.x;
    const int k = threadIdx.x;                        // 256 threads, 1 float4 each
    const float4 a = reinterpret_cast<const float4*>(img + (size_t)row * DIM)[k];
    const float4 b = reinterpret_cast<const float4*>(txt + (size_t)row * DIM)[k];

    reinterpret_cast<uint32_t*>(g_img_f8 + (size_t)row * DIM)[k] = pack4_e4m3(a);
    reinterpret_cast<uint32_t*>(g_txt_f8 + (size_t)row * DIM)[k] = pack4_e4m3(b);

    float si = a.x*a.x + a.y*a.y + a.z*a.z + a.w*a.w;
    float st = b.x*b.x + b.y*b.y + b.z*b.z + b.w*b.w;
    float sd = a.x*b.x + a.y*b.y + a.z*b.z + a.w*b.w;

    __shared__ float sh[3][8];
    int lane = threadIdx.x & 31, wid = threadIdx.x >> 5;
    si = warp_sum(si); st = warp_sum(st); sd = warp_sum(sd);
    if (lane == 0) { sh[0][wid] = si; sh[1][wid] = st; sh[2][wid] = sd; }
    __syncthreads();
    if (wid == 0) {
        si = (lane < 8) ? sh[0][lane] : 0.f;
        st = (lane < 8) ? sh[1][lane] : 0.f;
        sd = (lane < 8) ? sh[2][lane] : 0.f;
        #pragma unroll
        for (int o = 4; o > 0; o >>= 1) {
            si += __shfl_down_sync(0xffffffffu, si, o);
            st += __shfl_down_sync(0xffffffffu, st, o);
            sd += __shfl_down_sync(0xffffffffu, sd, o);
        }
        if (lane == 0) {
            float ni = fmaxf(sqrtf(si), EPSN);
            float nt = fmaxf(sqrtf(st), EPSN);
            g_rnorm_img[row] = 1.0f / ni;
            g_rnorm_txt[row] = 1.0f / nt;
            float e = 1.0f - sd / (ni * nt);
            g_pos_part[row] = e * e;
        }
    }
}

#define CP_ASYNC16(dst, src) \
    asm volatile("cp.async.cg.shared.global [%0], [%1], 16;" :: "r"(dst), "l"(src) : "memory")
#define CP_COMMIT()  asm volatile("cp.async.commit_group;" ::: "memory")
#define CP_WAIT()    asm volatile("cp.async.wait_group %0;" :: "n"(STAGES - 1) : "memory")

#define LDSM_X4(r0, r1, r2, r3, addr) \
    asm volatile("ldmatrix.sync.aligned.m8n8.x4.shared.b16 {%0,%1,%2,%3}, [%4];" \
        : "=r"(r0), "=r"(r1), "=r"(r2), "=r"(r3) : "r"(addr))

#define MMA_FP8(c, a, b) \
    asm volatile("mma.sync.aligned.m16n8k32.row.col.f32.e4m3.e4m3.f32 " \
        "{%0,%1,%2,%3}, {%4,%5,%6,%7}, {%8,%9}, {%0,%1,%2,%3};" \
        : "+f"((c)[0]), "+f"((c)[1]), "+f"((c)[2]), "+f"((c)[3]) \
        : "r"((a)[0]), "r"((a)[1]), "r"((a)[2]), "r"((a)[3]), "r"((b)[0]), "r"((b)[1]))

__device__ __forceinline__ void prefetch_stage(uint32_t sa, uint32_t sb, int bi, int bj,
                                               int kt, int tid)
{
    const int r  = tid >> 1;            // 0..127
    const int c0 = (tid & 1) * 2;       // 16B chunks c0, c0+1 (of 4 per 64B row)
    const uint8_t* asrc = g_img_f8 + (size_t)(bi + r) * DIM + kt * BK + c0 * 16;
    const uint8_t* bsrc = g_txt_f8 + (size_t)(bj + r) * DIM + kt * BK + c0 * 16;
    uint32_t da = sa + r * SROW + c0 * 16;
    uint32_t db = sb + r * SROW + c0 * 16;
    CP_ASYNC16(da,      asrc);
    CP_ASYNC16(da + 16, asrc + 16);
    CP_ASYNC16(db,      bsrc);
    CP_ASYNC16(db + 16, bsrc + 16);
}

__global__ void __launch_bounds__(256, 2) gemm_neg_kernel()
{
    extern __shared__ char smem[];
    const uint32_t sbase = smem_u32(smem);
    const int tid  = threadIdx.x;
    const int lane = tid & 31;
    const int wid  = tid >> 5;
    const int wm   = (wid >> 2) * 64;   // warp m offset (0 or 64)
    const int wn   = (wid & 3) * 32;    // warp n offset (0,32,64,96)

    const int bi = blockIdx.y * BM;
    const int bj = blockIdx.x * BN;

    uint32_t sA[STAGES], sB[STAGES];
    #pragma unroll
    for (int s = 0; s < STAGES; ++s) {
        sA[s] = sbase + s * STAGE_BYTES;
        sB[s] = sA[s] + STAGE_A;
    }

    float acc[4][4][4];
    #pragma unroll
    for (int i = 0; i < 4; ++i)
        #pragma unroll
        for (int j = 0; j < 4; ++j)
            #pragma unroll
            for (int k = 0; k < 4; ++k) acc[i][j][k] = 0.f;

    #pragma unroll
    for (int s = 0; s < STAGES; ++s) {
        prefetch_stage(sA[s], sB[s], bi, bj, s, tid);
        CP_COMMIT();
    }

    // ldmatrix lane addressing: uniform for A and B tiles
    // tile order for x4: t0=rows0-7/bytes0-15, t1=rows8-15/b0-15, t2=rows0-7/b16-31, t3=rows8-15/b16-31
    const int lrow  = (lane & 7) + ((lane >> 3) & 1) * 8;
    const int lboff = (lane >> 4) * 16;

    for (int kt = 0; kt < KT; ++kt) {
        const int st = kt % STAGES;
        CP_WAIT();
        __syncthreads();

        #pragma unroll
        for (int ks = 0; ks < 2; ++ks) {            // two k32 steps per 64B chunk
            uint32_t af[4][4], bf[4][2];
            #pragma unroll
            for (int mf = 0; mf < 4; ++mf) {
                uint32_t addr = sA[st] + (wm + mf * 16 + lrow) * SROW + ks * 32 + lboff;
                LDSM_X4(af[mf][0], af[mf][1], af[mf][2], af[mf][3], addr);
            }
            #pragma unroll
            for (int nf2 = 0; nf2 < 2; ++nf2) {
                uint32_t addr = sB[st] + (wn + nf2 * 16 + lrow) * SROW + ks * 32 + lboff;
                uint32_t r0, r1, r2, r3;
                LDSM_X4(r0, r1, r2, r3, addr);
                bf[nf2 * 2][0] = r0;     bf[nf2 * 2 + 1][0] = r1;
                bf[nf2 * 2][1] = r2;     bf[nf2 * 2 + 1][1] = r3;
            }
            #pragma unroll
            for (int mf = 0; mf < 4; ++mf)
                #pragma unroll
                for (int nf = 0; nf < 4; ++nf)
                    MMA_FP8(acc[mf][nf], af[mf], bf[nf]);
        }
        __syncthreads();

        if (kt + STAGES < KT)
            prefetch_stage(sA[st], sB[st], bi, bj, kt + STAGES, tid);
        CP_COMMIT();
    }

    // ---- fused loss epilogue ----
    const int groupRow = lane >> 2;        // 0..7
    const int col0 = (lane & 3) * 2;

    float rj[4][2];
    #pragma unroll
    for (int nf = 0; nf < 4; ++nf) {
        int gj = bj + wn + nf * 8 + col0;
        rj[nf][0] = __ldg(&g_rnorm_txt[gj]);
        rj[nf][1] = __ldg(&g_rnorm_txt[gj + 1]);
    }

    float local = 0.f;
    #pragma unroll
    for (int mf = 0; mf < 4; ++mf) {
        int gi0 = bi + wm + mf * 16 + groupRow;
        int gi1 = gi0 + 8;
        float ri0 = __ldg(&g_rnorm_img[gi0]);
        float ri1 = __ldg(&g_rnorm_img[gi1]);
        #pragma unroll
        for (int nf = 0; nf < 4; ++nf) {
            int gj0 = bj + wn + nf * 8 + col0;
            int gj1 = gj0 + 1;
            float s0 = acc[mf][nf][0] * ri0 * rj[nf][0];
            float s1 = acc[mf][nf][1] * ri0 * rj[nf][1];
            float s2 = acc[mf][nf][2] * ri1 * rj[nf][0];
            float s3 = acc[mf][nf][3] * ri1 * rj[nf][1];
            float d0 = s0 - MARGIN, d1 = s1 - MARGIN;
            float d2 = s2 - MARGIN, d3 = s3 - MARGIN;
            if (gi0 != gj0 && d0 > 0.f) local += d0 * d0;
            if (gi0 != gj1 && d1 > 0.f) local += d1 * d1;
            if (gi1 != gj0 && d2 > 0.f) local += d2 * d2;
            if (gi1 != gj1 && d3 > 0.f) local += d3 * d3;
        }
    }

    __shared__ float red[8];
    local = warp_sum(local);
    if (lane == 0) red[wid] = local;
    __syncthreads();
    if (wid == 0) {
        local = (lane < 8) ? red[lane] : 0.f;
        #pragma unroll
        for (int o = 4; o > 0; o >>= 1)
            local += __shfl_down_sync(0xffffffffu, local, o);
        if (lane == 0) g_neg_part[blockIdx.y * NBLK_J + blockIdx.x] = local;
    }
}

__global__ void __launch_bounds__(256) finalize_kernel(float* __restrict__ out) {
    const int tid = threadIdx.x;
    float sp = 0.f, sn = 0.f;
    #pragma unroll 4
    for (int i = tid; i < NROWS; i += 256) sp += g_pos_part[i];
    for (int i = tid; i < NBLK_I * NBLK_J; i += 256) sn += g_neg_part[i];

    __shared__ float shp[8], shn[8];
    int lane = tid & 31, wid = tid >> 5;
    sp = warp_sum(sp); sn = warp_sum(sn);
    if (lane == 0) { shp[wid] = sp; shn[wid] = sn; }
    __syncthreads();
    if (wid == 0) {
        sp = (lane < 8) ? shp[lane] : 0.f;
        sn = (lane < 8) ? shn[lane] : 0.f;
        #pragma unroll
        for (int o = 4; o > 0; o >>= 1) {
            sp += __shfl_down_sync(0xffffffffu, sp, o);
            sn += __shfl_down_sync(0xffffffffu, sn, o);
        }
        if (lane == 0) {
            const float n = (float)NROWS;
            out[0] = sp / n + sn / (n * n);
        }
    }
}

extern "C" void kernel_launch(void* const* d_in, const int* in_sizes, int n_in,
                              void* d_out, int out_size) {
    const float* img = (const float*)d_in[0];
    const float* txt = (const float*)d_in[1];
    float* out = (float*)d_out;

    cudaFuncSetAttribute(gemm_neg_kernel, cudaFuncAttributeMaxDynamicSharedMemorySize, SMEM_BYTES);

    row_stats_convert_kernel<<<NROWS, 256>>>(img, txt);
    dim3 grid(NBLK_J, NBLK_I);   // (32, 32)
    gemm_neg_kernel<<<grid, 256, SMEM_BYTES>>>();
    finalize_kernel<<<1, 256>>>(out);
}